// round 1
// baseline (speedup 1.0000x reference)
#include <cuda_runtime.h>
#include <math.h>

// Problem constants
#define BATCH 8
#define CH    128
#define HH    224
#define WW    224
#define OHH   112
#define OWW   112
#define KTOT  1152      // 128 channels * 9 taps, k = c*9 + (ky*3+kx)
#define KC    8         // K-chunk per smem stage

// Scratch for r_ = gelu(conv(r)+b)  [8,128,112,112] fp32
__device__ float g_rp[BATCH * CH * OHH * OWW];

__device__ __forceinline__ float gelu_exact(float x) {
    return 0.5f * x * (1.0f + erff(x * 0.7071067811865475f));
}

union F2U { float2 f; unsigned long long u; };

// Packed fp32x2 FMA (Blackwell). acc += a * b elementwise on 2 lanes.
__device__ __forceinline__ void ffma2(unsigned long long& acc,
                                      unsigned long long a,
                                      unsigned long long b) {
#if defined(__CUDA_ARCH__) && (__CUDA_ARCH__ >= 1000)
    asm("fma.rn.f32x2 %0, %1, %2, %0;" : "+l"(acc) : "l"(a), "l"(b));
#else
    F2U A, B, C; A.u = a; B.u = b; C.u = acc;
    C.f.x = fmaf(A.f.x, B.f.x, C.f.x);
    C.f.y = fmaf(A.f.y, B.f.y, C.f.y);
    acc = C.u;
#endif
}

// ---------------------------------------------------------------------------
// Kernel 1: implicit-GEMM conv (stride 2, 3x3, pad 1) + bias + exact GELU.
// CTA tile: 128 pixels (8 rows x 16 cols of output) x 64 output channels.
// 256 threads; per-thread micro-tile 8 px x 4 oc, accumulated as f32x2 pairs.
// ---------------------------------------------------------------------------
__global__ __launch_bounds__(256, 2)
void conv_gelu_kernel(const float* __restrict__ r,
                      const float* __restrict__ w,
                      const float* __restrict__ bias)
{
    __shared__ float  As[KC][128];    // [k][pixel]
    __shared__ float2 Bs[KC][65];     // [k][oc] duplicated {w,w}, padded row

    const int tid  = threadIdx.x;
    const int tile = blockIdx.x;              // 0..97  (14 x 7)
    const int oy0  = (tile / 7) * 8;
    const int ox0  = (tile % 7) * 16;
    const int oc0  = blockIdx.y * 64;         // 0 or 64
    const int b    = blockIdx.z;

    const float* rb = r + (size_t)b * CH * HH * WW;

    // --- A (im2col) load lanes: 4 elements/thread, lin = tid + i*256 ---
    int cA[4], tapA[4], iybase[4], ixbase[4];
#pragma unroll
    for (int i = 0; i < 4; i++) {
        int lin = tid + i * 256;              // [0,1024)
        int kk  = lin >> 7;                   // 0..7
        int px  = lin & 127;                  // 0..127
        int py  = px >> 4, pxx = px & 15;
        cA[i]   = 0;
        tapA[i] = kk;                         // k starts at kk (< 9)
        iybase[i] = 2 * (oy0 + py) - 1;
        ixbase[i] = 2 * (ox0 + pxx) - 1;
    }
    // --- B (weights) load lanes: 2 elements/thread ---
    int nB[2], kkB[2];
#pragma unroll
    for (int j = 0; j < 2; j++) {
        int lin = tid + j * 256;              // [0,512)
        nB[j]  = lin >> 3;                    // 0..63
        kkB[j] = lin & 7;                     // 0..7
    }

    const int tx  = tid & 15;
    const int tyy = tid >> 4;

    unsigned long long acc[4][4];             // [pixel-pair][oc]
#pragma unroll
    for (int p = 0; p < 4; p++)
#pragma unroll
        for (int n = 0; n < 4; n++) acc[p][n] = 0ull;

    float av[4], bvv[2];

    // Prefetch chunk 0
#pragma unroll
    for (int i = 0; i < 4; i++) {
        int tap = tapA[i];
        int ky  = (tap >= 6) ? 2 : ((tap >= 3) ? 1 : 0);
        int kx  = tap - ky * 3;
        int iy  = iybase[i] + ky;
        int ix  = ixbase[i] + kx;
        bool ok = ((unsigned)iy < HH) && ((unsigned)ix < WW);
        av[i] = ok ? __ldg(rb + cA[i] * (HH * WW) + iy * WW + ix) : 0.0f;
        tapA[i] += KC; if (tapA[i] >= 9) { tapA[i] -= 9; cA[i]++; }
    }
#pragma unroll
    for (int j = 0; j < 2; j++)
        bvv[j] = __ldg(w + (oc0 + nB[j]) * KTOT + kkB[j]);

    int k0 = 0;
    for (int kt = 0; kt < KTOT / KC; ++kt) {
        __syncthreads();
#pragma unroll
        for (int i = 0; i < 4; i++) {
            int lin = tid + i * 256;
            As[lin >> 7][lin & 127] = av[i];
        }
#pragma unroll
        for (int j = 0; j < 2; j++)
            Bs[kkB[j]][nB[j]] = make_float2(bvv[j], bvv[j]);
        __syncthreads();

        k0 += KC;
        if (kt + 1 < KTOT / KC) {
#pragma unroll
            for (int i = 0; i < 4; i++) {
                int tap = tapA[i];
                int ky  = (tap >= 6) ? 2 : ((tap >= 3) ? 1 : 0);
                int kx  = tap - ky * 3;
                int iy  = iybase[i] + ky;
                int ix  = ixbase[i] + kx;
                bool ok = ((unsigned)iy < HH) && ((unsigned)ix < WW);
                av[i] = ok ? __ldg(rb + cA[i] * (HH * WW) + iy * WW + ix) : 0.0f;
                tapA[i] += KC; if (tapA[i] >= 9) { tapA[i] -= 9; cA[i]++; }
            }
#pragma unroll
            for (int j = 0; j < 2; j++)
                bvv[j] = __ldg(w + (oc0 + nB[j]) * KTOT + k0 + kkB[j]);
        }

        // Compute KC k-steps from smem, packed f32x2
#pragma unroll
        for (int kk = 0; kk < KC; kk++) {
            F2U a0, a1, a2, a3;
            a0.f = *(const float2*)&As[kk][tx * 4];
            a1.f = *(const float2*)&As[kk][tx * 4 + 2];
            a2.f = *(const float2*)&As[kk][64 + tx * 4];
            a3.f = *(const float2*)&As[kk][64 + tx * 4 + 2];
            unsigned long long aa0 = a0.u, aa1 = a1.u, aa2 = a2.u, aa3 = a3.u;
#pragma unroll
            for (int n = 0; n < 4; n++) {
                F2U bb; bb.f = Bs[kk][tyy * 4 + n];
                ffma2(acc[0][n], aa0, bb.u);
                ffma2(acc[1][n], aa1, bb.u);
                ffma2(acc[2][n], aa2, bb.u);
                ffma2(acc[3][n], aa3, bb.u);
            }
        }
    }

    // Epilogue: bias + exact GELU, vectorized stores
    float bv[4];
#pragma unroll
    for (int n = 0; n < 4; n++) bv[n] = bias[oc0 + tyy * 4 + n];

    float* rp  = g_rp + (size_t)b * CH * OHH * OWW;
    const int py0 = tx >> 2;                 // row within group 0 (0..3)
    const int ox  = ox0 + (tx & 3) * 4;

#pragma unroll
    for (int n = 0; n < 4; n++) {
        int oc = oc0 + tyy * 4 + n;
        float* base = rp + (size_t)oc * OHH * OWW;
        F2U p0, p1, p2, p3;
        p0.u = acc[0][n]; p1.u = acc[1][n];
        p2.u = acc[2][n]; p3.u = acc[3][n];
        float4 v0, v1;
        v0.x = gelu_exact(p0.f.x + bv[n]);
        v0.y = gelu_exact(p0.f.y + bv[n]);
        v0.z = gelu_exact(p1.f.x + bv[n]);
        v0.w = gelu_exact(p1.f.y + bv[n]);
        v1.x = gelu_exact(p2.f.x + bv[n]);
        v1.y = gelu_exact(p2.f.y + bv[n]);
        v1.z = gelu_exact(p3.f.x + bv[n]);
        v1.w = gelu_exact(p3.f.y + bv[n]);
        *(float4*)&base[(oy0 + py0)     * OWW + ox] = v0;   // pixels 0..63 block
        *(float4*)&base[(oy0 + 4 + py0) * OWW + ox] = v1;   // pixels 64..127 block
    }
}

// ---------------------------------------------------------------------------
// Kernel 2: details = AvgPool2( MaxFilt3x3( r - NearestUp2(r_) ) ); out = r_ + details
// CTA: one (b,c) plane, 16 output rows x 112 cols. Full-res detail tile in smem.
// ---------------------------------------------------------------------------
__global__ __launch_bounds__(256)
void details_kernel(const float* __restrict__ r, float* __restrict__ out)
{
    __shared__ float ds[34][228];   // detail: rows y = 2*i0-1+yy, cols x = xx-1
    __shared__ float rs[18][112];   // r_ rows i0-1 .. i0+16

    const int tid   = threadIdx.x;
    const int strip = blockIdx.x;   // 0..6
    const int plane = blockIdx.y;   // 0..1023  (b*128 + c)
    const int i0    = strip * 16;

    const float* rfull = r    + (size_t)plane * (HH * WW);
    const float* rhalf = g_rp + (size_t)plane * (OHH * OWW);
    float*       obase = out  + (size_t)plane * (OHH * OWW);

    for (int idx = tid; idx < 18 * 112; idx += 256) {
        int rr  = idx / 112;
        int cc  = idx - rr * 112;
        int row = i0 - 1 + rr;
        rs[rr][cc] = ((unsigned)row < OHH) ? rhalf[row * OWW + cc] : 0.0f;
    }
    __syncthreads();

    const float NEGINF = __int_as_float(0xff800000);

    for (int idx = tid; idx < 34 * 226; idx += 256) {
        int yy = idx / 226;
        int xx = idx - yy * 226;
        int y  = 2 * i0 - 1 + yy;
        int x  = xx - 1;
        float d = NEGINF;
        if ((unsigned)y < HH && (unsigned)x < WW)
            d = rfull[y * WW + x] - rs[(y >> 1) - (i0 - 1)][x >> 1];
        ds[yy][xx] = d;
    }
    __syncthreads();

    for (int idx = tid; idx < 16 * 112; idx += 256) {
        int ii = idx / 112;
        int j  = idx - ii * 112;
        int ry = 2 * ii, rx = 2 * j;

        float d00 = ds[ry    ][rx], d01 = ds[ry    ][rx+1], d02 = ds[ry    ][rx+2], d03 = ds[ry    ][rx+3];
        float d10 = ds[ry + 1][rx], d11 = ds[ry + 1][rx+1], d12 = ds[ry + 1][rx+2], d13 = ds[ry + 1][rx+3];
        float d20 = ds[ry + 2][rx], d21 = ds[ry + 2][rx+1], d22 = ds[ry + 2][rx+2], d23 = ds[ry + 2][rx+3];
        float d30 = ds[ry + 3][rx], d31 = ds[ry + 3][rx+1], d32 = ds[ry + 3][rx+2], d33 = ds[ry + 3][rx+3];

        // column maxes over rows 0..2 (top) and 1..3 (bottom)
        float c0t = fmaxf(fmaxf(d00, d10), d20);
        float c1t = fmaxf(fmaxf(d01, d11), d21);
        float c2t = fmaxf(fmaxf(d02, d12), d22);
        float c3t = fmaxf(fmaxf(d03, d13), d23);
        float c0b = fmaxf(fmaxf(d10, d20), d30);
        float c1b = fmaxf(fmaxf(d11, d21), d31);
        float c2b = fmaxf(fmaxf(d12, d22), d32);
        float c3b = fmaxf(fmaxf(d13, d23), d33);

        float m00 = fmaxf(fmaxf(c0t, c1t), c2t);
        float m01 = fmaxf(fmaxf(c1t, c2t), c3t);
        float m10 = fmaxf(fmaxf(c0b, c1b), c2b);
        float m11 = fmaxf(fmaxf(c1b, c2b), c3b);

        float pooled = 0.25f * ((m00 + m01) + (m10 + m11));
        obase[(i0 + ii) * OWW + j] = rs[ii + 1][j] + pooled;
    }
}

// ---------------------------------------------------------------------------
extern "C" void kernel_launch(void* const* d_in, const int* in_sizes, int n_in,
                              void* d_out, int out_size)
{
    const float* r  = (const float*)d_in[0];
    const float* w  = (const float*)d_in[1];
    const float* b  = (const float*)d_in[2];
    float* out = (float*)d_out;

    dim3 g1(98, 2, BATCH);        // 14x7 pixel tiles, 2 oc halves, 8 batches
    conv_gelu_kernel<<<g1, 256>>>(r, w, b);

    dim3 g2(7, BATCH * CH);       // 7 row strips, 1024 (b,c) planes
    details_kernel<<<g2, 256>>>(r, out);
}

// round 4
// speedup vs baseline: 2.3348x; 2.3348x over previous
#include <cuda_runtime.h>
#include <cuda_bf16.h>
#include <math.h>
#include <stdint.h>

#define BATCH 8
#define CH    128
#define HH    224
#define WW    224
#define OHH   112
#define OWW   112
#define KTOT  1152          // k = c*9 + (ky*3+kx)
#define KC2   64            // k per chunk
#define NCHUNK (KTOT/KC2)   // 18

// Scratch
__device__ float         g_rp[BATCH * CH * OHH * OWW];   // r_ = gelu(conv+b)
__device__ __nv_bfloat16 g_wh[CH * KTOT];                // weight hi  [oc][k]
__device__ __nv_bfloat16 g_wl[CH * KTOT];                // weight lo  [oc][k]

// ---------------- helpers ----------------
__device__ __forceinline__ uint32_t s2u(const void* p) {
    uint32_t a;
    asm("{ .reg .u64 t; cvta.to.shared.u64 t, %1; cvt.u32.u64 %0, t; }"
        : "=r"(a) : "l"(p));
    return a;
}

#define SWZ(o) ((o) ^ ((((uint32_t)(o)) >> 3) & 0x70))

__device__ __forceinline__ void ldsm4(uint32_t* r, uint32_t addr) {
    asm volatile("ldmatrix.sync.aligned.m8n8.x4.shared.b16 {%0,%1,%2,%3}, [%4];"
                 : "=r"(r[0]), "=r"(r[1]), "=r"(r[2]), "=r"(r[3]) : "r"(addr));
}

__device__ __forceinline__ void mma_bf16(float* c, const uint32_t* a, const uint32_t* b) {
    asm volatile(
        "mma.sync.aligned.m16n8k16.row.col.f32.bf16.bf16.f32 "
        "{%0,%1,%2,%3}, {%4,%5,%6,%7}, {%8,%9}, {%0,%1,%2,%3};"
        : "+f"(c[0]), "+f"(c[1]), "+f"(c[2]), "+f"(c[3])
        : "r"(a[0]), "r"(a[1]), "r"(a[2]), "r"(a[3]), "r"(b[0]), "r"(b[1]));
}

__device__ __forceinline__ float gelu_exact(float x) {
    return 0.5f * x * (1.0f + erff(x * 0.70710678118654752f));
}

// ---------------- SMEM layout (dynamic) ----------------
// [0,512)    bias
// [1024)     Ah 16K | Al 16K | Bh 16K | Bl 16K   (single stage)
#define OFF_AH 1024
#define OFF_AL (OFF_AH + 16384)
#define OFF_BH (OFF_AH + 32768)
#define OFF_BL (OFF_AH + 49152)
#define SMEM_TOTAL (1024 + 65536)

// ---------------------------------------------------------------------------
// Weight prep: fp32 -> bf16 hi/lo split. w layout [oc][ic][3][3] == [oc][k].
// ---------------------------------------------------------------------------
__global__ void wprep_kernel(const float* __restrict__ w) {
    int i = blockIdx.x * 256 + threadIdx.x;
    if (i < CH * KTOT) {
        float v = w[i];
        __nv_bfloat16 h = __float2bfloat16(v);
        g_wh[i] = h;
        g_wl[i] = __float2bfloat16(v - __bfloat162float(h));
    }
}

// ---------------------------------------------------------------------------
// Conv (3x3, stride 2, pad 1) as warp-MMA GEMM: D[128px,128oc], K=1152.
// bf16 hi/lo split, 3 passes (hh + hl + lh). Epilogue: bias + exact GELU.
// 8 warps, each owns 64px x 32oc.
// ---------------------------------------------------------------------------
__global__ __launch_bounds__(256, 2)
void conv_mma_kernel(const float* __restrict__ r, const float* __restrict__ bias)
{
    extern __shared__ char smc[];
    const uint32_t sb = s2u(smc);
    const int tid  = threadIdx.x;
    const int wid  = tid >> 5;
    const int lane = tid & 31;
    const int tile = blockIdx.x;              // 0..97 = 14 x 7
    const int b    = blockIdx.z;
    const int oy0  = (tile / 7) * 8;
    const int ox0  = (tile % 7) * 16;
    const float* rb = r + (size_t)b * CH * HH * WW;

    if (tid < 128) ((float*)(smc))[tid] = bias[tid];

    const int warp_m = wid & 1;               // 0..1  (64 px each)
    const int warp_n = wid >> 1;              // 0..3  (32 oc each)

    // ldmatrix lane address components
    const int aRow = lane & 15;                       // row within 16
    const int aKb  = (lane >> 4) << 4;                // 0 or 16 bytes
    const int bRow = (lane & 7) + ((lane >> 4) << 3); // n within 16
    const int bKb  = ((lane >> 3) & 1) << 4;          // 0 or 16 bytes

    // A-fill lane mapping: pixel + 8-k runs
    const int pxme = ((wid & 3) << 5) | lane;         // 0..127
    const int iy0  = 2 * (oy0 + (pxme >> 4)) - 1;
    const int ix0  = 2 * (ox0 + (pxme & 15)) - 1;

    float acc[4][4][4];
#pragma unroll
    for (int mi = 0; mi < 4; mi++)
#pragma unroll
        for (int ni = 0; ni < 4; ni++)
#pragma unroll
            for (int q = 0; q < 4; q++) acc[mi][ni][q] = 0.0f;

#pragma unroll 1
    for (int ch_ = 0; ch_ < NCHUNK; ch_++) {
        const int kc0 = ch_ * KC2;
        __syncthreads();   // previous chunk's compute done

        // ---- fill A: thread handles 8 consecutive k for one pixel, x4 ----
#pragma unroll
        for (int i = 0; i < 4; i++) {
            const int g  = (wid >> 2) + 2 * i;    // 0..7
            const int kk = g << 3;
            int k   = kc0 + kk;
            int c   = k / 9;
            int tap = k - 9 * c;
            float v[8];
#pragma unroll
            for (int e = 0; e < 8; e++) {
                const int ky = tap / 3;
                const int kx = tap - 3 * ky;
                const int iy = iy0 + ky;
                const int ix = ix0 + kx;
                float vv = 0.0f;
                if ((unsigned)iy < HH && (unsigned)ix < WW)
                    vv = __ldg(rb + c * (HH * WW) + iy * WW + ix);
                v[e] = vv;
                if (++tap == 9) { tap = 0; c++; }
            }
            uint32_t hq[4], lq[4];
#pragma unroll
            for (int e = 0; e < 4; e++) {
                __nv_bfloat16 h0 = __float2bfloat16(v[2 * e]);
                __nv_bfloat16 h1 = __float2bfloat16(v[2 * e + 1]);
                __nv_bfloat16 l0 = __float2bfloat16(v[2 * e]     - __bfloat162float(h0));
                __nv_bfloat16 l1 = __float2bfloat16(v[2 * e + 1] - __bfloat162float(h1));
                __nv_bfloat162 hp; hp.x = h0; hp.y = h1;
                __nv_bfloat162 lp; lp.x = l0; lp.y = l1;
                hq[e] = *(uint32_t*)&hp;
                lq[e] = *(uint32_t*)&lp;
            }
            const uint32_t off = SWZ(pxme * 128 + kk * 2);
            *(uint4*)(smc + OFF_AH + off) = make_uint4(hq[0], hq[1], hq[2], hq[3]);
            *(uint4*)(smc + OFF_AL + off) = make_uint4(lq[0], lq[1], lq[2], lq[3]);
        }

        // ---- fill B: thread copies 8 k (16B) for one oc, x4 ----
#pragma unroll
        for (int i = 0; i < 4; i++) {
            const int oc = (tid >> 3) + (i << 5);
            const int g  = tid & 7;
            const size_t eoff = (size_t)oc * KTOT + kc0 + g * 8;
            uint4 h = __ldg((const uint4*)((const char*)g_wh + 2 * eoff));
            uint4 l = __ldg((const uint4*)((const char*)g_wl + 2 * eoff));
            const uint32_t off = SWZ(oc * 128 + g * 16);
            *(uint4*)(smc + OFF_BH + off) = h;
            *(uint4*)(smc + OFF_BL + off) = l;
        }
        __syncthreads();

        // ---- compute: 4 k16-steps, passes hh, hl, lh ----
#pragma unroll
        for (int ks = 0; ks < 4; ks++) {
            const int kb = ks * 32;
            uint32_t af[4][4], bhf[8], blf[8];

            // A-hi frags (4 m-tiles of 16)
#pragma unroll
            for (int mi = 0; mi < 4; mi++) {
                const int row = warp_m * 64 + mi * 16 + aRow;
                ldsm4(af[mi], sb + OFF_AH + SWZ(row * 128 + kb + aKb));
            }
            // B-hi frags (2 x ldsm.x4 covering 32 oc)
#pragma unroll
            for (int h = 0; h < 2; h++) {
                const int row = warp_n * 32 + h * 16 + bRow;
                ldsm4(&bhf[h * 4], sb + OFF_BH + SWZ(row * 128 + kb + bKb));
            }
#pragma unroll
            for (int mi = 0; mi < 4; mi++)
#pragma unroll
                for (int ni = 0; ni < 4; ni++)
                    mma_bf16(acc[mi][ni], af[mi], &bhf[ni * 2]);

            // B-lo frags, pass hl
#pragma unroll
            for (int h = 0; h < 2; h++) {
                const int row = warp_n * 32 + h * 16 + bRow;
                ldsm4(&blf[h * 4], sb + OFF_BL + SWZ(row * 128 + kb + bKb));
            }
#pragma unroll
            for (int mi = 0; mi < 4; mi++)
#pragma unroll
                for (int ni = 0; ni < 4; ni++)
                    mma_bf16(acc[mi][ni], af[mi], &blf[ni * 2]);

            // A-lo frags (reuse af), pass lh
#pragma unroll
            for (int mi = 0; mi < 4; mi++) {
                const int row = warp_m * 64 + mi * 16 + aRow;
                ldsm4(af[mi], sb + OFF_AL + SWZ(row * 128 + kb + aKb));
            }
#pragma unroll
            for (int mi = 0; mi < 4; mi++)
#pragma unroll
                for (int ni = 0; ni < 4; ni++)
                    mma_bf16(acc[mi][ni], af[mi], &bhf[ni * 2]);
        }
    }

    // ---- epilogue: bias + exact GELU ----
    const int qrow = lane >> 2;          // 0..7
    const int qcol = (lane & 3) * 2;     // 0,2,4,6
    float bv[4][2];
    {
        const float* bs = (const float*)smc;
#pragma unroll
        for (int ni = 0; ni < 4; ni++) {
            bv[ni][0] = bs[warp_n * 32 + ni * 8 + qcol];
            bv[ni][1] = bs[warp_n * 32 + ni * 8 + qcol + 1];
        }
    }
    float* rpb = g_rp + (size_t)b * CH * OHH * OWW;
#pragma unroll
    for (int mi = 0; mi < 4; mi++) {
#pragma unroll
        for (int half = 0; half < 2; half++) {
            const int m  = warp_m * 64 + mi * 16 + qrow + half * 8;
            const int py = m >> 4, px = m & 15;
            float* base = rpb + (size_t)(oy0 + py) * OWW + (ox0 + px);
#pragma unroll
            for (int ni = 0; ni < 4; ni++) {
                const int oc = warp_n * 32 + ni * 8 + qcol;
                float v0 = gelu_exact(acc[mi][ni][half * 2]     + bv[ni][0]);
                float v1 = gelu_exact(acc[mi][ni][half * 2 + 1] + bv[ni][1]);
                base[(size_t)oc       * (OHH * OWW)] = v0;
                base[(size_t)(oc + 1) * (OHH * OWW)] = v1;
            }
        }
    }
}

// ---------------------------------------------------------------------------
// details = AvgPool2( MaxFilt3x3( r - NearestUp2(r_) ) ); out = r_ + details
// Warp-per-row structure, no div/mod in hot loops.
// ---------------------------------------------------------------------------
__global__ __launch_bounds__(256, 1)
void details_kernel(const float* __restrict__ r, float* __restrict__ out)
{
    __shared__ float ds[34][228];
    __shared__ float rs[18][112];

    const int tid   = threadIdx.x;
    const int wid   = tid >> 5;
    const int lane  = tid & 31;
    const int strip = blockIdx.x;     // 0..6
    const int plane = blockIdx.y;     // b*128 + c
    const int i0    = strip * 16;

    const float* rfull = r    + (size_t)plane * (HH * WW);
    const float* rhalf = g_rp + (size_t)plane * (OHH * OWW);
    float*       obase = out  + (size_t)plane * (OHH * OWW);

    // rs: 18 rows x 28 float4
    for (int rr = wid; rr < 18; rr += 8) {
        const int row = i0 - 1 + rr;
        if (lane < 28) {
            float4 v = make_float4(0.f, 0.f, 0.f, 0.f);
            if ((unsigned)row < OHH)
                v = *(const float4*)(rhalf + row * OWW + lane * 4);
            *(float4*)(&rs[rr][lane * 4]) = v;
        }
    }
    __syncthreads();

    // ds: detail with -inf border, rows y = 2*i0-1+yy, cols x = xx-1
    for (int yy = wid; yy < 34; yy += 8) {
        const int y    = 2 * i0 - 1 + yy;
        const bool yok = ((unsigned)y < HH);
        const float* rrow  = rfull + (ptrdiff_t)y * WW;
        const int rsr = (y >> 1) - (i0 - 1);           // 0..17
        const float* rsrow = &rs[rsr][0];
        for (int xx = lane; xx < 226; xx += 32) {
            const int x = xx - 1;
            float d = __int_as_float(0xff800000);      // -inf
            if (yok && (unsigned)x < WW)
                d = rrow[x] - rsrow[x >> 1];
            ds[yy][xx] = d;
        }
    }
    __syncthreads();

    // output: 3x3 max at 4 positions + avgpool2 + residual
    for (int ii = wid; ii < 16; ii += 8) {
        const int ry = 2 * ii;
        const float* d0 = &ds[ry][0];
        const float* d1 = &ds[ry + 1][0];
        const float* d2 = &ds[ry + 2][0];
        const float* d3 = &ds[ry + 3][0];
        float* orow = obase + (size_t)(i0 + ii) * OWW;
        const float* rsrow = &rs[ii + 1][0];
        for (int j = lane; j < 112; j += 32) {
            const int rx = 2 * j;
            float2 a0 = *(const float2*)(d0 + rx), a1 = *(const float2*)(d0 + rx + 2);
            float2 b0 = *(const float2*)(d1 + rx), b1 = *(const float2*)(d1 + rx + 2);
            float2 c0 = *(const float2*)(d2 + rx), c1 = *(const float2*)(d2 + rx + 2);
            float2 e0 = *(const float2*)(d3 + rx), e1 = *(const float2*)(d3 + rx + 2);

            float c0t = fmaxf(fmaxf(a0.x, b0.x), c0.x);
            float c1t = fmaxf(fmaxf(a0.y, b0.y), c0.y);
            float c2t = fmaxf(fmaxf(a1.x, b1.x), c1.x);
            float c3t = fmaxf(fmaxf(a1.y, b1.y), c1.y);
            float c0b = fmaxf(fmaxf(b0.x, c0.x), e0.x);
            float c1b = fmaxf(fmaxf(b0.y, c0.y), e0.y);
            float c2b = fmaxf(fmaxf(b1.x, c1.x), e1.x);
            float c3b = fmaxf(fmaxf(b1.y, c1.y), e1.y);

            float m00 = fmaxf(fmaxf(c0t, c1t), c2t);
            float m01 = fmaxf(fmaxf(c1t, c2t), c3t);
            float m10 = fmaxf(fmaxf(c0b, c1b), c2b);
            float m11 = fmaxf(fmaxf(c1b, c2b), c3b);

            orow[j] = rsrow[j] + 0.25f * ((m00 + m01) + (m10 + m11));
        }
    }
}

// ---------------------------------------------------------------------------
extern "C" void kernel_launch(void* const* d_in, const int* in_sizes, int n_in,
                              void* d_out, int out_size)
{
    const float* r  = (const float*)d_in[0];
    const float* w  = (const float*)d_in[1];
    const float* b  = (const float*)d_in[2];
    float* out = (float*)d_out;

    cudaFuncSetAttribute(conv_mma_kernel,
                         cudaFuncAttributeMaxDynamicSharedMemorySize, SMEM_TOTAL);

    wprep_kernel<<<(CH * KTOT + 255) / 256, 256>>>(w);
    conv_mma_kernel<<<dim3(98, 1, BATCH), 256, SMEM_TOTAL>>>(r, b);
    details_kernel<<<dim3(7, BATCH * CH), 256>>>(r, out);
}

// round 6
// speedup vs baseline: 3.3503x; 1.4350x over previous
#include <cuda_runtime.h>
#include <cuda_fp16.h>
#include <math.h>
#include <stdint.h>

#define BATCH 8
#define CH    128
#define HH    224
#define WW    224
#define OHH   112
#define OWW   112
#define KTOT  1152          // k = c*9 + (ky*3+kx)
#define KC    32            // k per chunk
#define NCHUNK (KTOT/KC)    // 36

// Scratch
__device__ float  g_rp[BATCH * CH * OHH * OWW];   // r_ = gelu(conv+b)
__device__ __half g_wh[CH * KTOT];                // weight hi  [oc][k]
__device__ __half g_wl[CH * KTOT];                // weight lo  [oc][k]

// ---------------- helpers ----------------
__device__ __forceinline__ uint32_t s2u(const void* p) {
    uint32_t a;
    asm("{ .reg .u64 t; cvta.to.shared.u64 t, %1; cvt.u32.u64 %0, t; }"
        : "=r"(a) : "l"(p));
    return a;
}

// SW64 swizzle for 64-byte rows
#define SWZ64(o) ((o) ^ ((((uint32_t)(o)) >> 3) & 0x30))

__device__ __forceinline__ void ldsm4(uint32_t* r, uint32_t addr) {
    asm volatile("ldmatrix.sync.aligned.m8n8.x4.shared.b16 {%0,%1,%2,%3}, [%4];"
                 : "=r"(r[0]), "=r"(r[1]), "=r"(r[2]), "=r"(r[3]) : "r"(addr));
}

__device__ __forceinline__ void mma_f16(float* c, const uint32_t* a, const uint32_t* b) {
    asm volatile(
        "mma.sync.aligned.m16n8k16.row.col.f32.f16.f16.f32 "
        "{%0,%1,%2,%3}, {%4,%5,%6,%7}, {%8,%9}, {%0,%1,%2,%3};"
        : "+f"(c[0]), "+f"(c[1]), "+f"(c[2]), "+f"(c[3])
        : "r"(a[0]), "r"(a[1]), "r"(a[2]), "r"(a[3]), "r"(b[0]), "r"(b[1]));
}

__device__ __forceinline__ void cp_async16(uint32_t dst, const void* src) {
    asm volatile("cp.async.cg.shared.global [%0], [%1], 16;"
                 :: "r"(dst), "l"(src));
}
__device__ __forceinline__ void cp_commit() {
    asm volatile("cp.async.commit_group;");
}
__device__ __forceinline__ void cp_wait0() {
    asm volatile("cp.async.wait_group 0;");
}

__device__ __forceinline__ float gelu_exact(float x) {
    return 0.5f * x * (1.0f + erff(x * 0.70710678118654752f));
}

// ---------------- SMEM layout (dynamic) ----------------
// [0,512)  bias
// stage s at 1024 + s*24576:  A(8K) | Bh(8K) | Bl(8K)
#define OFF_A(s)  (1024 + (s) * 24576)
#define OFF_BH(s) (OFF_A(s) + 8192)
#define OFF_BL(s) (OFF_A(s) + 16384)
#define SMEM_TOTAL (1024 + 2 * 24576)

// ---------------------------------------------------------------------------
// Weight prep: fp32 -> fp16 hi/lo split. w layout [oc][ic][3][3] == [oc][k].
// ---------------------------------------------------------------------------
__global__ void wprep_kernel(const float* __restrict__ w) {
    int i = blockIdx.x * 256 + threadIdx.x;
    if (i < CH * KTOT) {
        float v = w[i];
        __half h = __float2half_rn(v);
        g_wh[i] = h;
        g_wl[i] = __float2half_rn(v - __half2float(h));
    }
}

// ---------------------------------------------------------------------------
// Conv (3x3, stride 2, pad 1) as warp-MMA GEMM: D[128px,128oc], K=1152.
// A fp16, B fp16 hi/lo, 2 passes (A*Bh + A*Bl). Double-buffered, pipelined.
// 8 warps, each owns 64px x 32oc. Epilogue: bias + exact GELU.
// ---------------------------------------------------------------------------
__global__ __launch_bounds__(256, 2)
void conv_mma_kernel(const float* __restrict__ r, const float* __restrict__ bias)
{
    extern __shared__ char smc[];
    const uint32_t sb = s2u(smc);
    const int tid  = threadIdx.x;
    const int wid  = tid >> 5;
    const int lane = tid & 31;
    const int tile = blockIdx.x;              // 0..97 = 14 x 7
    const int b    = blockIdx.z;
    const int oy0  = (tile / 7) * 8;
    const int ox0  = (tile % 7) * 16;
    const float* rb = r + (size_t)b * CH * HH * WW;

    if (tid < 128) ((float*)(smc))[tid] = bias[tid];

    const int warp_m = wid & 1;               // 0..1  (64 px each)
    const int warp_n = wid >> 1;              // 0..3  (32 oc each)

    // ldmatrix lane address components
    const int aRow = lane & 15;                       // row within 16
    const int aKb  = (lane >> 4) << 4;                // 0 or 16 bytes
    const int bRow = (lane & 7) + ((lane >> 4) << 3); // n within 16
    const int bKb  = ((lane >> 3) & 1) << 4;          // 0 or 16 bytes

    // A-fill mapping: px = tid&127 (lane-consecutive), khalf = tid>>7
    const int pxA   = tid & 127;
    const int khalf = tid >> 7;               // 0 or 1 -> k offset 0/16
    const int iy0   = 2 * (oy0 + (pxA >> 4)) - 1;
    const int ix0   = 2 * (ox0 + (pxA & 15)) - 1;
    const uint32_t aStOff0 = SWZ64(pxA * 64 + khalf * 32);
    const uint32_t aStOff1 = SWZ64(pxA * 64 + khalf * 32 + 16);

    // B-fill (cp.async) mapping: oc = tid>>1, two 16B ops per matrix
    const int ocB = tid >> 1;
    const int jB  = (tid & 1) * 2;            // j, j+1  (16B units within 64B row)

    float acc[4][4][4];
#pragma unroll
    for (int mi = 0; mi < 4; mi++)
#pragma unroll
        for (int ni = 0; ni < 4; ni++)
#pragma unroll
            for (int q = 0; q < 4; q++) acc[mi][ni][q] = 0.0f;

    float v[16];   // staged A gather for the upcoming chunk

    // ---- prologue: gather A(0), cp.async B(0) into stage 0 ----
    {
        int k = khalf * 16;
        int c = k / 9, tap = k - 9 * c;
#pragma unroll
        for (int e = 0; e < 16; e++) {
            const int ky = tap / 3;
            const int kx = tap - 3 * ky;
            const int iy = iy0 + ky;
            const int ix = ix0 + kx;
            float vv = 0.0f;
            if ((unsigned)iy < HH && (unsigned)ix < WW)
                vv = __ldg(rb + c * (HH * WW) + iy * WW + ix);
            v[e] = vv;
            if (++tap == 9) { tap = 0; c++; }
        }
#pragma unroll
        for (int j = 0; j < 2; j++) {
            const size_t eoff = (size_t)ocB * KTOT + (jB + j) * 8;
            const uint32_t doff = SWZ64(ocB * 64 + (jB + j) * 16);
            cp_async16(sb + OFF_BH(0) + doff, (const char*)g_wh + 2 * eoff);
            cp_async16(sb + OFF_BL(0) + doff, (const char*)g_wl + 2 * eoff);
        }
        cp_commit();
    }

#pragma unroll 1
    for (int ch_ = 0; ch_ < NCHUNK; ch_++) {
        const int s = ch_ & 1;

        // ---- store staged A into bufA[s] ----
        {
            uint32_t hq[8];
#pragma unroll
            for (int e = 0; e < 8; e++) {
                __half2 p = __floats2half2_rn(v[2 * e], v[2 * e + 1]);
                hq[e] = *(uint32_t*)&p;
            }
            *(uint4*)(smc + OFF_A(s) + aStOff0) = make_uint4(hq[0], hq[1], hq[2], hq[3]);
            *(uint4*)(smc + OFF_A(s) + aStOff1) = make_uint4(hq[4], hq[5], hq[6], hq[7]);
        }
        cp_wait0();          // B(ch) arrived
        __syncthreads();     // A stored + B visible to all warps

        // ---- issue fills for chunk ch+1 (hidden under MMA below) ----
        if (ch_ + 1 < NCHUNK) {
            const int kc1 = (ch_ + 1) * KC;
            int k = kc1 + khalf * 16;
            int c = k / 9, tap = k - 9 * c;
#pragma unroll
            for (int e = 0; e < 16; e++) {
                const int ky = tap / 3;
                const int kx = tap - 3 * ky;
                const int iy = iy0 + ky;
                const int ix = ix0 + kx;
                float vv = 0.0f;
                if ((unsigned)iy < HH && (unsigned)ix < WW)
                    vv = __ldg(rb + c * (HH * WW) + iy * WW + ix);
                v[e] = vv;
                if (++tap == 9) { tap = 0; c++; }
            }
#pragma unroll
            for (int j = 0; j < 2; j++) {
                const size_t eoff = (size_t)ocB * KTOT + kc1 + (jB + j) * 8;
                const uint32_t doff = SWZ64(ocB * 64 + (jB + j) * 16);
                cp_async16(sb + OFF_BH(s ^ 1) + doff, (const char*)g_wh + 2 * eoff);
                cp_async16(sb + OFF_BL(s ^ 1) + doff, (const char*)g_wl + 2 * eoff);
            }
            cp_commit();
        }

        // ---- compute: 2 k16-steps, passes hh then hl ----
#pragma unroll
        for (int ks = 0; ks < 2; ks++) {
            const int kb = ks * 32;
            uint32_t af[4][4], bhf[8], blf[8];
#pragma unroll
            for (int mi = 0; mi < 4; mi++) {
                const int row = warp_m * 64 + mi * 16 + aRow;
                ldsm4(af[mi], sb + OFF_A(s) + SWZ64(row * 64 + kb + aKb));
            }
#pragma unroll
            for (int h = 0; h < 2; h++) {
                const int row = warp_n * 32 + h * 16 + bRow;
                ldsm4(&bhf[h * 4], sb + OFF_BH(s) + SWZ64(row * 64 + kb + bKb));
            }
#pragma unroll
            for (int mi = 0; mi < 4; mi++)
#pragma unroll
                for (int ni = 0; ni < 4; ni++)
                    mma_f16(acc[mi][ni], af[mi], &bhf[ni * 2]);
#pragma unroll
            for (int h = 0; h < 2; h++) {
                const int row = warp_n * 32 + h * 16 + bRow;
                ldsm4(&blf[h * 4], sb + OFF_BL(s) + SWZ64(row * 64 + kb + bKb));
            }
#pragma unroll
            for (int mi = 0; mi < 4; mi++)
#pragma unroll
                for (int ni = 0; ni < 4; ni++)
                    mma_f16(acc[mi][ni], af[mi], &blf[ni * 2]);
        }
    }

    // ---- epilogue: bias + exact GELU ----
    const int qrow = lane >> 2;          // 0..7
    const int qcol = (lane & 3) * 2;     // 0,2,4,6
    float bv[4][2];
    {
        const float* bs = (const float*)smc;
#pragma unroll
        for (int ni = 0; ni < 4; ni++) {
            bv[ni][0] = bs[warp_n * 32 + ni * 8 + qcol];
            bv[ni][1] = bs[warp_n * 32 + ni * 8 + qcol + 1];
        }
    }
    float* rpb = g_rp + (size_t)b * CH * OHH * OWW;
#pragma unroll
    for (int mi = 0; mi < 4; mi++) {
#pragma unroll
        for (int half = 0; half < 2; half++) {
            const int m  = warp_m * 64 + mi * 16 + qrow + half * 8;
            const int py = m >> 4, px = m & 15;
            float* base = rpb + (size_t)(oy0 + py) * OWW + (ox0 + px);
#pragma unroll
            for (int ni = 0; ni < 4; ni++) {
                const int oc = warp_n * 32 + ni * 8 + qcol;
                float v0 = gelu_exact(acc[mi][ni][half * 2]     + bv[ni][0]);
                float v1 = gelu_exact(acc[mi][ni][half * 2 + 1] + bv[ni][1]);
                base[(size_t)oc       * (OHH * OWW)] = v0;
                base[(size_t)(oc + 1) * (OHH * OWW)] = v1;
            }
        }
    }
}

// ---------------------------------------------------------------------------
// details = AvgPool2( MaxFilt3x3( r - NearestUp2(r_) ) ); out = r_ + details
// ---------------------------------------------------------------------------
__global__ __launch_bounds__(256, 1)
void details_kernel(const float* __restrict__ r, float* __restrict__ out)
{
    __shared__ float ds[34][228];
    __shared__ float rs[18][112];

    const int tid   = threadIdx.x;
    const int wid   = tid >> 5;
    const int lane  = tid & 31;
    const int strip = blockIdx.x;     // 0..6
    const int plane = blockIdx.y;     // b*128 + c
    const int i0    = strip * 16;

    const float* rfull = r    + (size_t)plane * (HH * WW);
    const float* rhalf = g_rp + (size_t)plane * (OHH * OWW);
    float*       obase = out  + (size_t)plane * (OHH * OWW);

    for (int rr = wid; rr < 18; rr += 8) {
        const int row = i0 - 1 + rr;
        if (lane < 28) {
            float4 vv = make_float4(0.f, 0.f, 0.f, 0.f);
            if ((unsigned)row < OHH)
                vv = *(const float4*)(rhalf + row * OWW + lane * 4);
            *(float4*)(&rs[rr][lane * 4]) = vv;
        }
    }
    __syncthreads();

    for (int yy = wid; yy < 34; yy += 8) {
        const int y    = 2 * i0 - 1 + yy;
        const bool yok = ((unsigned)y < HH);
        const float* rrow  = rfull + (ptrdiff_t)y * WW;
        const int rsr = (y >> 1) - (i0 - 1);
        const float* rsrow = &rs[rsr][0];
        for (int xx = lane; xx < 226; xx += 32) {
            const int x = xx - 1;
            float d = __int_as_float(0xff800000);
            if (yok && (unsigned)x < WW)
                d = rrow[x] - rsrow[x >> 1];
            ds[yy][xx] = d;
        }
    }
    __syncthreads();

    for (int ii = wid; ii < 16; ii += 8) {
        const int ry = 2 * ii;
        const float* d0 = &ds[ry][0];
        const float* d1 = &ds[ry + 1][0];
        const float* d2 = &ds[ry + 2][0];
        const float* d3 = &ds[ry + 3][0];
        float* orow = obase + (size_t)(i0 + ii) * OWW;
        const float* rsrow = &rs[ii + 1][0];
        for (int j = lane; j < 112; j += 32) {
            const int rx = 2 * j;
            float2 a0 = *(const float2*)(d0 + rx), a1 = *(const float2*)(d0 + rx + 2);
            float2 b0 = *(const float2*)(d1 + rx), b1 = *(const float2*)(d1 + rx + 2);
            float2 c0 = *(const float2*)(d2 + rx), c1 = *(const float2*)(d2 + rx + 2);
            float2 e0 = *(const float2*)(d3 + rx), e1 = *(const float2*)(d3 + rx + 2);

            float c0t = fmaxf(fmaxf(a0.x, b0.x), c0.x);
            float c1t = fmaxf(fmaxf(a0.y, b0.y), c0.y);
            float c2t = fmaxf(fmaxf(a1.x, b1.x), c1.x);
            float c3t = fmaxf(fmaxf(a1.y, b1.y), c1.y);
            float c0b = fmaxf(fmaxf(b0.x, c0.x), e0.x);
            float c1b = fmaxf(fmaxf(b0.y, c0.y), e0.y);
            float c2b = fmaxf(fmaxf(b1.x, c1.x), e1.x);
            float c3b = fmaxf(fmaxf(b1.y, c1.y), e1.y);

            float m00 = fmaxf(fmaxf(c0t, c1t), c2t);
            float m01 = fmaxf(fmaxf(c1t, c2t), c3t);
            float m10 = fmaxf(fmaxf(c0b, c1b), c2b);
            float m11 = fmaxf(fmaxf(c1b, c2b), c3b);

            orow[j] = rsrow[j] + 0.25f * ((m00 + m01) + (m10 + m11));
        }
    }
}

// ---------------------------------------------------------------------------
extern "C" void kernel_launch(void* const* d_in, const int* in_sizes, int n_in,
                              void* d_out, int out_size)
{
    const float* r  = (const float*)d_in[0];
    const float* w  = (const float*)d_in[1];
    const float* b  = (const float*)d_in[2];
    float* out = (float*)d_out;

    cudaFuncSetAttribute(conv_mma_kernel,
                         cudaFuncAttributeMaxDynamicSharedMemorySize, SMEM_TOTAL);

    wprep_kernel<<<(CH * KTOT + 255) / 256, 256>>>(w);
    conv_mma_kernel<<<dim3(98, 1, BATCH), 256, SMEM_TOTAL>>>(r, b);
    details_kernel<<<dim3(7, BATCH * CH), 256>>>(r, out);
}

// round 7
// speedup vs baseline: 4.3353x; 1.2940x over previous
#include <cuda_runtime.h>
#include <cuda_fp16.h>
#include <math.h>
#include <stdint.h>

#define BATCH 8
#define CH    128
#define HH    224
#define WW    224
#define OHH   112
#define OWW   112
#define KTOT  1152          // k = c*9 + (ky*3+kx)
#define KC    32            // k per chunk
#define NCHUNK (KTOT/KC)    // 36

// Scratch
__device__ float  g_rp[BATCH * CH * OHH * OWW];   // r_ = gelu(conv+b)
__device__ __half g_wh[CH * KTOT];                // weight fp16 [oc][k]

// ---------------- helpers ----------------
__device__ __forceinline__ uint32_t s2u(const void* p) {
    uint32_t a;
    asm("{ .reg .u64 t; cvta.to.shared.u64 t, %1; cvt.u32.u64 %0, t; }"
        : "=r"(a) : "l"(p));
    return a;
}

// SW64 swizzle for 64-byte rows
#define SWZ64(o) ((o) ^ ((((uint32_t)(o)) >> 3) & 0x30))

__device__ __forceinline__ void ldsm4(uint32_t* r, uint32_t addr) {
    asm volatile("ldmatrix.sync.aligned.m8n8.x4.shared.b16 {%0,%1,%2,%3}, [%4];"
                 : "=r"(r[0]), "=r"(r[1]), "=r"(r[2]), "=r"(r[3]) : "r"(addr));
}

__device__ __forceinline__ void mma_f16(float* c, const uint32_t* a, const uint32_t* b) {
    asm volatile(
        "mma.sync.aligned.m16n8k16.row.col.f32.f16.f16.f32 "
        "{%0,%1,%2,%3}, {%4,%5,%6,%7}, {%8,%9}, {%0,%1,%2,%3};"
        : "+f"(c[0]), "+f"(c[1]), "+f"(c[2]), "+f"(c[3])
        : "r"(a[0]), "r"(a[1]), "r"(a[2]), "r"(a[3]), "r"(b[0]), "r"(b[1]));
}

__device__ __forceinline__ void cp_async16(uint32_t dst, const void* src) {
    asm volatile("cp.async.cg.shared.global [%0], [%1], 16;"
                 :: "r"(dst), "l"(src));
}
__device__ __forceinline__ void cp_commit() {
    asm volatile("cp.async.commit_group;");
}
__device__ __forceinline__ void cp_wait0() {
    asm volatile("cp.async.wait_group 0;");
}

__device__ __forceinline__ float gelu_exact(float x) {
    return 0.5f * x * (1.0f + erff(x * 0.70710678118654752f));
}

// ---------------- SMEM layout (dynamic) ----------------
// [0,512)  bias
// stage s at 1024 + s*16384:  A(8K) | B(8K)
#define OFF_A(s)  (1024 + (s) * 16384)
#define OFF_B(s)  (OFF_A(s) + 8192)
#define SMEM_TOTAL (1024 + 2 * 16384)

// ---------------------------------------------------------------------------
// Weight prep: fp32 -> fp16. w layout [oc][ic][3][3] == [oc][k].
// ---------------------------------------------------------------------------
__global__ void wprep_kernel(const float* __restrict__ w) {
    int i = blockIdx.x * 256 + threadIdx.x;
    if (i < CH * KTOT)
        g_wh[i] = __float2half_rn(w[i]);
}

// ---------------------------------------------------------------------------
// Conv (3x3, stride 2, pad 1) as warp-MMA GEMM: D[128px,128oc], K=1152.
// fp16 single pass, fp32 accumulate. Double-buffered, pipelined.
// 8 warps, each owns 64px x 32oc. Epilogue: bias + exact GELU.
// ---------------------------------------------------------------------------
__global__ __launch_bounds__(256, 2)
void conv_mma_kernel(const float* __restrict__ r, const float* __restrict__ bias)
{
    extern __shared__ char smc[];
    const uint32_t sb = s2u(smc);
    const int tid  = threadIdx.x;
    const int wid  = tid >> 5;
    const int lane = tid & 31;
    const int tile = blockIdx.x;              // 0..97 = 14 x 7
    const int b    = blockIdx.z;
    const int oy0  = (tile / 7) * 8;
    const int ox0  = (tile % 7) * 16;
    const float* rb = r + (size_t)b * CH * HH * WW;

    if (tid < 128) ((float*)(smc))[tid] = bias[tid];

    const int warp_m = wid & 1;               // 0..1  (64 px each)
    const int warp_n = wid >> 1;              // 0..3  (32 oc each)

    // ldmatrix lane address components
    const int aRow = lane & 15;                       // row within 16
    const int aKb  = (lane >> 4) << 4;                // 0 or 16 bytes
    const int bRow = (lane & 7) + ((lane >> 4) << 3); // n within 16
    const int bKb  = ((lane >> 3) & 1) << 4;          // 0 or 16 bytes

    // A-fill mapping: px = tid&127 (lane-consecutive), khalf = tid>>7
    const int pxA   = tid & 127;
    const int khalf = tid >> 7;               // 0 or 1 -> k offset 0/16
    const int iy0   = 2 * (oy0 + (pxA >> 4)) - 1;
    const int ix0   = 2 * (ox0 + (pxA & 15)) - 1;
    const uint32_t aStOff0 = SWZ64(pxA * 64 + khalf * 32);
    const uint32_t aStOff1 = SWZ64(pxA * 64 + khalf * 32 + 16);

    // B-fill (cp.async) mapping: oc = tid>>1, two 16B ops
    const int ocB = tid >> 1;
    const int jB  = (tid & 1) * 2;            // 16B units within 64B row

    float acc[4][4][4];
#pragma unroll
    for (int mi = 0; mi < 4; mi++)
#pragma unroll
        for (int ni = 0; ni < 4; ni++)
#pragma unroll
            for (int q = 0; q < 4; q++) acc[mi][ni][q] = 0.0f;

    float v[16];   // staged A gather for the upcoming chunk

    // ---- prologue: gather A(0), cp.async B(0) into stage 0 ----
    {
        int k = khalf * 16;
        int c = k / 9, tap = k - 9 * c;
#pragma unroll
        for (int e = 0; e < 16; e++) {
            const int ky = tap / 3;
            const int kx = tap - 3 * ky;
            const int iy = iy0 + ky;
            const int ix = ix0 + kx;
            float vv = 0.0f;
            if ((unsigned)iy < HH && (unsigned)ix < WW)
                vv = __ldg(rb + c * (HH * WW) + iy * WW + ix);
            v[e] = vv;
            if (++tap == 9) { tap = 0; c++; }
        }
#pragma unroll
        for (int j = 0; j < 2; j++) {
            const size_t eoff = (size_t)ocB * KTOT + (jB + j) * 8;
            const uint32_t doff = SWZ64(ocB * 64 + (jB + j) * 16);
            cp_async16(sb + OFF_B(0) + doff, (const char*)g_wh + 2 * eoff);
        }
        cp_commit();
    }

#pragma unroll 1
    for (int ch_ = 0; ch_ < NCHUNK; ch_++) {
        const int s = ch_ & 1;

        // ---- store staged A into bufA[s] ----
        {
            uint32_t hq[8];
#pragma unroll
            for (int e = 0; e < 8; e++) {
                __half2 p = __floats2half2_rn(v[2 * e], v[2 * e + 1]);
                hq[e] = *(uint32_t*)&p;
            }
            *(uint4*)(smc + OFF_A(s) + aStOff0) = make_uint4(hq[0], hq[1], hq[2], hq[3]);
            *(uint4*)(smc + OFF_A(s) + aStOff1) = make_uint4(hq[4], hq[5], hq[6], hq[7]);
        }
        cp_wait0();          // B(ch) arrived
        __syncthreads();     // A stored + B visible to all warps

        // ---- issue fills for chunk ch+1 (hidden under MMA below) ----
        if (ch_ + 1 < NCHUNK) {
            const int kc1 = (ch_ + 1) * KC;
            int k = kc1 + khalf * 16;
            int c = k / 9, tap = k - 9 * c;
#pragma unroll
            for (int e = 0; e < 16; e++) {
                const int ky = tap / 3;
                const int kx = tap - 3 * ky;
                const int iy = iy0 + ky;
                const int ix = ix0 + kx;
                float vv = 0.0f;
                if ((unsigned)iy < HH && (unsigned)ix < WW)
                    vv = __ldg(rb + c * (HH * WW) + iy * WW + ix);
                v[e] = vv;
                if (++tap == 9) { tap = 0; c++; }
            }
#pragma unroll
            for (int j = 0; j < 2; j++) {
                const size_t eoff = (size_t)ocB * KTOT + kc1 + (jB + j) * 8;
                const uint32_t doff = SWZ64(ocB * 64 + (jB + j) * 16);
                cp_async16(sb + OFF_B(s ^ 1) + doff, (const char*)g_wh + 2 * eoff);
            }
            cp_commit();
        }

        // ---- compute: 2 k16-steps, single fp16 pass ----
#pragma unroll
        for (int ks = 0; ks < 2; ks++) {
            const int kb = ks * 32;
            uint32_t af[4][4], bf[8];
#pragma unroll
            for (int mi = 0; mi < 4; mi++) {
                const int row = warp_m * 64 + mi * 16 + aRow;
                ldsm4(af[mi], sb + OFF_A(s) + SWZ64(row * 64 + kb + aKb));
            }
#pragma unroll
            for (int h = 0; h < 2; h++) {
                const int row = warp_n * 32 + h * 16 + bRow;
                ldsm4(&bf[h * 4], sb + OFF_B(s) + SWZ64(row * 64 + kb + bKb));
            }
#pragma unroll
            for (int mi = 0; mi < 4; mi++)
#pragma unroll
                for (int ni = 0; ni < 4; ni++)
                    mma_f16(acc[mi][ni], af[mi], &bf[ni * 2]);
        }
    }

    // ---- epilogue: bias + exact GELU ----
    const int qrow = lane >> 2;          // 0..7
    const int qcol = (lane & 3) * 2;     // 0,2,4,6
    float bv[4][2];
    {
        const float* bs = (const float*)smc;
#pragma unroll
        for (int ni = 0; ni < 4; ni++) {
            bv[ni][0] = bs[warp_n * 32 + ni * 8 + qcol];
            bv[ni][1] = bs[warp_n * 32 + ni * 8 + qcol + 1];
        }
    }
    float* rpb = g_rp + (size_t)b * CH * OHH * OWW;
#pragma unroll
    for (int mi = 0; mi < 4; mi++) {
#pragma unroll
        for (int half = 0; half < 2; half++) {
            const int m  = warp_m * 64 + mi * 16 + qrow + half * 8;
            const int py = m >> 4, px = m & 15;
            float* base = rpb + (size_t)(oy0 + py) * OWW + (ox0 + px);
#pragma unroll
            for (int ni = 0; ni < 4; ni++) {
                const int oc = warp_n * 32 + ni * 8 + qcol;
                float v0 = gelu_exact(acc[mi][ni][half * 2]     + bv[ni][0]);
                float v1 = gelu_exact(acc[mi][ni][half * 2 + 1] + bv[ni][1]);
                base[(size_t)oc       * (OHH * OWW)] = v0;
                base[(size_t)(oc + 1) * (OHH * OWW)] = v1;
            }
        }
    }
}

// ---------------------------------------------------------------------------
// details = AvgPool2( MaxFilt3x3( r - NearestUp2(r_) ) ); out = r_ + details
// Strip of 8 output rows per CTA (21 KB smem -> 8 CTAs/SM).
// Warp w fills ds rows w, w+8, w+16(w<2); outputs row w.
// ---------------------------------------------------------------------------
__global__ __launch_bounds__(256)
void details_kernel(const float* __restrict__ r, float* __restrict__ out)
{
    __shared__ float ds[18][228];   // detail rows y = 2*i0-1+yy, col xx = x+1
    __shared__ float rs[10][112];   // r_ rows i0-1 .. i0+8

    const int tid   = threadIdx.x;
    const int wid   = tid >> 5;
    const int lane  = tid & 31;
    const int strip = blockIdx.x;   // 0..13
    const int plane = blockIdx.y;   // b*128 + c
    const int i0    = strip * 8;

    const float* rfull = r    + (size_t)plane * (HH * WW);
    const float* rhalf = g_rp + (size_t)plane * (OHH * OWW);
    float*       obase = out  + (size_t)plane * (OHH * OWW);

    // rs: 10 rows x 28 float4
    for (int rr = wid; rr < 10; rr += 8) {
        const int row = i0 - 1 + rr;
        if (lane < 28) {
            float4 vv = make_float4(0.f, 0.f, 0.f, 0.f);
            if ((unsigned)row < OHH)
                vv = *(const float4*)(rhalf + row * OWW + lane * 4);
            *(float4*)(&rs[rr][lane * 4]) = vv;
        }
    }
    __syncthreads();

    const float NEGINF = __int_as_float(0xff800000);

    // ds: interior branch-free (7 iters), borders by 2 lanes
    for (int yy = wid; yy < 18; yy += 8) {
        const int y    = 2 * i0 - 1 + yy;
        const bool yok = ((unsigned)y < HH);
        const float* rrow  = rfull + (ptrdiff_t)y * WW;
        const int rsr = (y >> 1) - (i0 - 1);        // 0..9 (y=-1 -> 0, unused)
        const float* rsrow = &rs[rsr][0];
        if (yok) {
#pragma unroll
            for (int it = 0; it < 7; it++) {
                const int x = lane + it * 32;       // 0..223
                ds[yy][x + 1] = rrow[x] - rsrow[x >> 1];
            }
        } else {
#pragma unroll
            for (int it = 0; it < 7; it++)
                ds[yy][lane + it * 32 + 1] = NEGINF;
        }
        if (lane == 0) ds[yy][0]   = NEGINF;
        if (lane == 1) ds[yy][225] = NEGINF;
    }
    __syncthreads();

    // output: warp wid handles output row i0+wid
    {
        const int ii = wid;
        const int ry = 2 * ii;
        const float* d0 = &ds[ry][0];
        const float* d1 = &ds[ry + 1][0];
        const float* d2 = &ds[ry + 2][0];
        const float* d3 = &ds[ry + 3][0];
        float* orow = obase + (size_t)(i0 + ii) * OWW;
        const float* rsrow = &rs[ii + 1][0];
        for (int j = lane; j < 112; j += 32) {
            const int rx = 2 * j;
            float2 a0 = *(const float2*)(d0 + rx), a1 = *(const float2*)(d0 + rx + 2);
            float2 b0 = *(const float2*)(d1 + rx), b1 = *(const float2*)(d1 + rx + 2);
            float2 c0 = *(const float2*)(d2 + rx), c1 = *(const float2*)(d2 + rx + 2);
            float2 e0 = *(const float2*)(d3 + rx), e1 = *(const float2*)(d3 + rx + 2);

            float c0t = fmaxf(fmaxf(a0.x, b0.x), c0.x);
            float c1t = fmaxf(fmaxf(a0.y, b0.y), c0.y);
            float c2t = fmaxf(fmaxf(a1.x, b1.x), c1.x);
            float c3t = fmaxf(fmaxf(a1.y, b1.y), c1.y);
            float c0b = fmaxf(fmaxf(b0.x, c0.x), e0.x);
            float c1b = fmaxf(fmaxf(b0.y, c0.y), e0.y);
            float c2b = fmaxf(fmaxf(b1.x, c1.x), e1.x);
            float c3b = fmaxf(fmaxf(b1.y, c1.y), e1.y);

            float m00 = fmaxf(fmaxf(c0t, c1t), c2t);
            float m01 = fmaxf(fmaxf(c1t, c2t), c3t);
            float m10 = fmaxf(fmaxf(c0b, c1b), c2b);
            float m11 = fmaxf(fmaxf(c1b, c2b), c3b);

            orow[j] = rsrow[j] + 0.25f * ((m00 + m01) + (m10 + m11));
        }
    }
}

// ---------------------------------------------------------------------------
extern "C" void kernel_launch(void* const* d_in, const int* in_sizes, int n_in,
                              void* d_out, int out_size)
{
    const float* r  = (const float*)d_in[0];
    const float* w  = (const float*)d_in[1];
    const float* b  = (const float*)d_in[2];
    float* out = (float*)d_out;

    cudaFuncSetAttribute(conv_mma_kernel,
                         cudaFuncAttributeMaxDynamicSharedMemorySize, SMEM_TOTAL);

    wprep_kernel<<<(CH * KTOT + 255) / 256, 256>>>(w);
    conv_mma_kernel<<<dim3(98, 1, BATCH), 256, SMEM_TOTAL>>>(r, b);
    details_kernel<<<dim3(14, BATCH * CH), 256>>>(r, out);
}